// round 5
// baseline (speedup 1.0000x reference)
#include <cuda_runtime.h>
#include <cstdint>

// Problem shape (fixed by reference)
#define T_DIM 16384
#define B_DIM 64
#define E_DIM 4096

// Scratch: __device__ globals (allocation-free, per harness rules)
__device__ float g_alpha[T_DIM];
__device__ float g_beta[T_DIM];
__device__ float g_A[T_DIM];
__device__ float g_B[T_DIM];

// ---------------------------------------------------------------------------
// Kernel 1: per-t gather + reduce over B=64.
// One warp per t. Each lane handles 2 entries; float2 gather from params
// (8 MB table -> L2-resident), warp shuffle reduce.
// NOTE: indices are int32 (JAX x64 disabled downcasts the int64 request).
// ---------------------------------------------------------------------------
__global__ void gather_reduce_kernel(const int* __restrict__ indices,
                                     const float* __restrict__ params) {
    int gwarp = (blockIdx.x * blockDim.x + threadIdx.x) >> 5;
    int lane  = threadIdx.x & 31;
    if (gwarp >= T_DIM) return;

    // coalesced: each lane reads a pair of adjacent int32 indices
    const int2* row2 = (const int2*)(indices + (size_t)gwarp * B_DIM);
    int2 idx = row2[lane];

    const float2* p2 = (const float2*)params;
    float2 a0 = __ldg(&p2[idx.x]);
    float2 a1 = __ldg(&p2[idx.y]);
    float sa = a0.x + a1.x;
    float sb = a0.y + a1.y;

    #pragma unroll
    for (int off = 16; off > 0; off >>= 1) {
        sa += __shfl_xor_sync(0xFFFFFFFFu, sa, off);
        sb += __shfl_xor_sync(0xFFFFFFFFu, sb, off);
    }
    if (lane == 0) {
        g_alpha[gwarp] = sa;
        g_beta[gwarp]  = sb;
    }
}

// ---------------------------------------------------------------------------
// Kernel 2: linear-recurrence scan over T=16384.
// Single block, 1024 threads, 16 elements/thread.
// Compose (ordered!):  combine(left=(A,B), elem=(a,b)) = (a*A, a*B + b)
// ---------------------------------------------------------------------------
__global__ void scan_kernel() {
    __shared__ float sA[1024];
    __shared__ float sB[1024];

    const int tid  = threadIdx.x;
    const int base = tid * 16;

    float la[16], lb[16];
    #pragma unroll
    for (int i = 0; i < 16; i++) {
        la[i] = g_alpha[base + i];
        lb[i] = g_beta[base + i];
    }

    // thread-local inclusive aggregate
    float ca = 1.0f, cb = 0.0f;
    #pragma unroll
    for (int i = 0; i < 16; i++) {
        cb = fmaf(la[i], cb, lb[i]);
        ca = la[i] * ca;
    }
    sA[tid] = ca;
    sB[tid] = cb;
    __syncthreads();

    // Hillis-Steele inclusive scan over 1024 aggregates (order-preserving)
    #pragma unroll
    for (int off = 1; off < 1024; off <<= 1) {
        float pa = 1.0f, pb = 0.0f;
        if (tid >= off) { pa = sA[tid - off]; pb = sB[tid - off]; }
        __syncthreads();
        if (tid >= off) {
            float ma = sA[tid], mb = sB[tid];
            sA[tid] = ma * pa;
            sB[tid] = fmaf(ma, pb, mb);
        }
        __syncthreads();
    }

    // exclusive prefix for this thread
    float pa = (tid > 0) ? sA[tid - 1] : 1.0f;
    float pb = (tid > 0) ? sB[tid - 1] : 0.0f;

    // replay local elements applying prefix; write full A/B arrays
    #pragma unroll
    for (int i = 0; i < 16; i++) {
        pb = fmaf(la[i], pb, lb[i]);
        pa = la[i] * pa;
        g_A[base + i] = pa;
        g_B[base + i] = pb;
    }
}

// ---------------------------------------------------------------------------
// Kernel 3: output broadcast.  out[t, e] = A[t] * M_prev[e] + B[t]
// One block per t-row; float4 loads of M_prev (L1-resident) + float4 stores.
// 268 MB of stores -> this kernel is the HBM roofline.
// ---------------------------------------------------------------------------
__global__ void __launch_bounds__(256) broadcast_kernel(
        const float* __restrict__ M_prev, float* __restrict__ out) {
    const int t = blockIdx.x;
    const float a = g_A[t];
    const float b = g_B[t];

    const float4* M4 = (const float4*)M_prev;
    float4* o4 = (float4*)(out + (size_t)t * E_DIM);

    #pragma unroll
    for (int k = 0; k < (E_DIM / 4) / 256; k++) {
        int i = k * 256 + threadIdx.x;
        float4 m = __ldg(&M4[i]);
        float4 r;
        r.x = fmaf(a, m.x, b);
        r.y = fmaf(a, m.y, b);
        r.z = fmaf(a, m.z, b);
        r.w = fmaf(a, m.w, b);
        o4[i] = r;
    }
}

// ---------------------------------------------------------------------------
extern "C" void kernel_launch(void* const* d_in, const int* in_sizes, int n_in,
                              void* d_out, int out_size) {
    const int*   indices = (const int*)d_in[0];   // (T, B) int32 (JAX downcast)
    const float* M_prev  = (const float*)d_in[1]; // (E,)   f32
    const float* params  = (const float*)d_in[2]; // (N, 2) f32
    float*       out     = (float*)d_out;         // (T, E) f32

    // K1: 16384 warps -> 8 warps/block -> 2048 blocks
    gather_reduce_kernel<<<(T_DIM * 32) / 256, 256>>>(indices, params);

    // K2: single-block scan
    scan_kernel<<<1, 1024>>>();

    // K3: one block per t-row
    broadcast_kernel<<<T_DIM, 256>>>(M_prev, out);
}

// round 6
// speedup vs baseline: 1.0204x; 1.0204x over previous
#include <cuda_runtime.h>
#include <cstdint>

// Problem shape (fixed by reference)
#define T_DIM 16384
#define B_DIM 64
#define E_DIM 4096

// Scratch: __device__ globals (allocation-free, per harness rules)
__device__ float g_alpha[T_DIM];
__device__ float g_beta[T_DIM];
__device__ float g_A[T_DIM];
__device__ float g_B[T_DIM];

// ---------------------------------------------------------------------------
// Kernel 1: per-t gather + reduce over B=64.
// One warp per FOUR t-rows -> 8 independent float2 gathers in flight per lane
// (was 2). Params table (8 MB) is L2-resident; kernel is gather-latency bound,
// so MLP is the lever.
// ---------------------------------------------------------------------------
#define K1_ROWS 4
__global__ void gather_reduce_kernel(const int* __restrict__ indices,
                                     const float* __restrict__ params) {
    int gwarp = (blockIdx.x * blockDim.x + threadIdx.x) >> 5;
    int lane  = threadIdx.x & 31;
    int t0 = gwarp * K1_ROWS;
    if (t0 >= T_DIM) return;

    const float2* p2 = (const float2*)params;

    // issue all index loads first (coalesced int2 per row)
    int2 idx[K1_ROWS];
    #pragma unroll
    for (int r = 0; r < K1_ROWS; r++) {
        idx[r] = ((const int2*)(indices + (size_t)(t0 + r) * B_DIM))[lane];
    }

    // issue all 8 gathers back-to-back (max MLP)
    float2 v0[K1_ROWS], v1[K1_ROWS];
    #pragma unroll
    for (int r = 0; r < K1_ROWS; r++) v0[r] = __ldg(&p2[idx[r].x]);
    #pragma unroll
    for (int r = 0; r < K1_ROWS; r++) v1[r] = __ldg(&p2[idx[r].y]);

    #pragma unroll
    for (int r = 0; r < K1_ROWS; r++) {
        float sa = v0[r].x + v1[r].x;
        float sb = v0[r].y + v1[r].y;
        #pragma unroll
        for (int off = 16; off > 0; off >>= 1) {
            sa += __shfl_xor_sync(0xFFFFFFFFu, sa, off);
            sb += __shfl_xor_sync(0xFFFFFFFFu, sb, off);
        }
        if (lane == 0) {
            g_alpha[t0 + r] = sa;
            g_beta[t0 + r]  = sb;
        }
    }
}

// ---------------------------------------------------------------------------
// Kernel 2: linear-recurrence scan over T=16384.
// Single block, 1024 threads, 16 elements/thread.
// Compose (ordered!):  combine(left=(A,B), elem=(a,b)) = (a*A, a*B + b)
// ---------------------------------------------------------------------------
__global__ void scan_kernel() {
    __shared__ float sA[1024];
    __shared__ float sB[1024];

    const int tid  = threadIdx.x;
    const int base = tid * 16;

    float la[16], lb[16];
    #pragma unroll
    for (int i = 0; i < 16; i++) {
        la[i] = g_alpha[base + i];
        lb[i] = g_beta[base + i];
    }

    // thread-local inclusive aggregate
    float ca = 1.0f, cb = 0.0f;
    #pragma unroll
    for (int i = 0; i < 16; i++) {
        cb = fmaf(la[i], cb, lb[i]);
        ca = la[i] * ca;
    }
    sA[tid] = ca;
    sB[tid] = cb;
    __syncthreads();

    // Hillis-Steele inclusive scan over 1024 aggregates (order-preserving)
    #pragma unroll
    for (int off = 1; off < 1024; off <<= 1) {
        float pa = 1.0f, pb = 0.0f;
        if (tid >= off) { pa = sA[tid - off]; pb = sB[tid - off]; }
        __syncthreads();
        if (tid >= off) {
            float ma = sA[tid], mb = sB[tid];
            sA[tid] = ma * pa;
            sB[tid] = fmaf(ma, pb, mb);
        }
        __syncthreads();
    }

    // exclusive prefix for this thread
    float pa = (tid > 0) ? sA[tid - 1] : 1.0f;
    float pb = (tid > 0) ? sB[tid - 1] : 0.0f;

    // replay local elements applying prefix; write full A/B arrays
    #pragma unroll
    for (int i = 0; i < 16; i++) {
        pb = fmaf(la[i], pb, lb[i]);
        pa = la[i] * pa;
        g_A[base + i] = pa;
        g_B[base + i] = pb;
    }
}

// ---------------------------------------------------------------------------
// Kernel 3: output broadcast.  out[t, e] = A[t] * M_prev[e] + B[t]
// Block = one E-chunk (1024 floats, held in registers as float4) x 16 t-rows.
// A/B staged to shared once per block; 16 fully independent row-stores per
// thread -> deep STG.128 stream. __stcs: output (268 MB) is write-once and
// 2x L2 capacity, so evict-first avoids dirty-line thrash.
// ---------------------------------------------------------------------------
#define K3_ROWS   16
#define K3_CHUNKS (E_DIM / (256 * 4))   // 4 column chunks of 1024 floats

__global__ void __launch_bounds__(256) broadcast_kernel(
        const float* __restrict__ M_prev, float* __restrict__ out) {
    __shared__ float sA[K3_ROWS];
    __shared__ float sB[K3_ROWS];

    const int t0 = blockIdx.y * K3_ROWS;
    if (threadIdx.x < K3_ROWS) {
        sA[threadIdx.x] = g_A[t0 + threadIdx.x];
    } else if (threadIdx.x < 2 * K3_ROWS) {
        sB[threadIdx.x - K3_ROWS] = g_B[t0 + threadIdx.x - K3_ROWS];
    }

    const int col = blockIdx.x * 256 + threadIdx.x;   // float4 column index
    float4 m = __ldg(&((const float4*)M_prev)[col]);
    __syncthreads();

    float4* o4 = (float4*)out;
    #pragma unroll
    for (int r = 0; r < K3_ROWS; r++) {
        float a = sA[r];
        float b = sB[r];
        float4 v;
        v.x = fmaf(a, m.x, b);
        v.y = fmaf(a, m.y, b);
        v.z = fmaf(a, m.z, b);
        v.w = fmaf(a, m.w, b);
        __stcs(&o4[(size_t)(t0 + r) * (E_DIM / 4) + col], v);
    }
}

// ---------------------------------------------------------------------------
extern "C" void kernel_launch(void* const* d_in, const int* in_sizes, int n_in,
                              void* d_out, int out_size) {
    const int*   indices = (const int*)d_in[0];   // (T, B) int32 (JAX downcast)
    const float* M_prev  = (const float*)d_in[1]; // (E,)   f32
    const float* params  = (const float*)d_in[2]; // (N, 2) f32
    float*       out     = (float*)d_out;         // (T, E) f32

    // K1: 4096 warps (4 rows each) -> 8 warps/block -> 512 blocks
    gather_reduce_kernel<<<(T_DIM / K1_ROWS * 32) / 256, 256>>>(indices, params);

    // K2: single-block scan
    scan_kernel<<<1, 1024>>>();

    // K3: (4 column chunks) x (1024 row groups)
    dim3 g3(K3_CHUNKS, T_DIM / K3_ROWS);
    broadcast_kernel<<<g3, 256>>>(M_prev, out);
}

// round 7
// speedup vs baseline: 1.4056x; 1.3775x over previous
#include <cuda_runtime.h>
#include <cstdint>

// Problem shape (fixed by reference)
#define T_DIM 16384
#define B_DIM 64
#define E_DIM 4096

// Permuted scratch layout so the single-block scan kernel is fully coalesced:
//   P(t) = (t & 15) * 1024 + (t >> 4)
// K2 thread `tid` owns elements t = 16*tid + i (i=0..15), whose permuted
// addresses are i*1024 + tid -> one coalesced 128B access per instruction.
__device__ __forceinline__ int PERM(int t) { return ((t & 15) << 10) | (t >> 4); }

// Scratch: __device__ globals (allocation-free, per harness rules)
__device__ float g_alpha[T_DIM];
__device__ float g_beta[T_DIM];
__device__ float g_A[T_DIM];
__device__ float g_B[T_DIM];

// ---------------------------------------------------------------------------
// Kernel 1: per-t gather + reduce over B=64.
// One warp per 4 t-rows, 8 independent float2 gathers per lane. Bound by the
// L1tex wavefront path for random 32B-sector gathers (~8us structural floor).
// ---------------------------------------------------------------------------
#define K1_ROWS 4
__global__ void gather_reduce_kernel(const int* __restrict__ indices,
                                     const float* __restrict__ params) {
    int gwarp = (blockIdx.x * blockDim.x + threadIdx.x) >> 5;
    int lane  = threadIdx.x & 31;
    int t0 = gwarp * K1_ROWS;
    if (t0 >= T_DIM) return;

    const float2* p2 = (const float2*)params;

    int2 idx[K1_ROWS];
    #pragma unroll
    for (int r = 0; r < K1_ROWS; r++) {
        idx[r] = ((const int2*)(indices + (size_t)(t0 + r) * B_DIM))[lane];
    }

    float2 v0[K1_ROWS], v1[K1_ROWS];
    #pragma unroll
    for (int r = 0; r < K1_ROWS; r++) v0[r] = __ldg(&p2[idx[r].x]);
    #pragma unroll
    for (int r = 0; r < K1_ROWS; r++) v1[r] = __ldg(&p2[idx[r].y]);

    #pragma unroll
    for (int r = 0; r < K1_ROWS; r++) {
        float sa = v0[r].x + v1[r].x;
        float sb = v0[r].y + v1[r].y;
        #pragma unroll
        for (int off = 16; off > 0; off >>= 1) {
            sa += __shfl_xor_sync(0xFFFFFFFFu, sa, off);
            sb += __shfl_xor_sync(0xFFFFFFFFu, sb, off);
        }
        if (lane == 0) {
            int p = PERM(t0 + r);
            g_alpha[p] = sa;
            g_beta[p]  = sb;
        }
    }
}

// ---------------------------------------------------------------------------
// Kernel 2: linear-recurrence scan over T=16384.
// Single block, 1024 threads, 16 elements/thread. All global accesses go
// through the permuted layout -> every warp load/store is one coalesced
// 128B transaction (was 16-32 wavefronts per strided instruction).
// Compose (ordered!): combine(left=(A,B), elem=(a,b)) = (a*A, a*B + b)
// ---------------------------------------------------------------------------
__global__ void scan_kernel() {
    __shared__ float sA[1024];
    __shared__ float sB[1024];

    const int tid = threadIdx.x;

    float la[16], lb[16];
    #pragma unroll
    for (int i = 0; i < 16; i++) {
        la[i] = g_alpha[i * 1024 + tid];   // == g_alpha[PERM(16*tid+i)]
        lb[i] = g_beta[i * 1024 + tid];
    }

    // thread-local inclusive aggregate over the contiguous chunk
    float ca = 1.0f, cb = 0.0f;
    #pragma unroll
    for (int i = 0; i < 16; i++) {
        cb = fmaf(la[i], cb, lb[i]);
        ca = la[i] * ca;
    }
    sA[tid] = ca;
    sB[tid] = cb;
    __syncthreads();

    // Hillis-Steele inclusive scan over 1024 aggregates (order-preserving)
    #pragma unroll
    for (int off = 1; off < 1024; off <<= 1) {
        float pa = 1.0f, pb = 0.0f;
        if (tid >= off) { pa = sA[tid - off]; pb = sB[tid - off]; }
        __syncthreads();
        if (tid >= off) {
            float ma = sA[tid], mb = sB[tid];
            sA[tid] = ma * pa;
            sB[tid] = fmaf(ma, pb, mb);
        }
        __syncthreads();
    }

    // exclusive prefix for this thread
    float pa = (tid > 0) ? sA[tid - 1] : 1.0f;
    float pb = (tid > 0) ? sB[tid - 1] : 0.0f;

    // replay local elements applying prefix; coalesced permuted writes
    #pragma unroll
    for (int i = 0; i < 16; i++) {
        pb = fmaf(la[i], pb, lb[i]);
        pa = la[i] * pa;
        g_A[i * 1024 + tid] = pa;
        g_B[i * 1024 + tid] = pb;
    }
}

// ---------------------------------------------------------------------------
// Kernel 3: output broadcast.  out[t, e] = A[t] * M_prev[e] + B[t]
// Block = one E-chunk (1024 floats as float4) x 16 t-rows. A/B staged to
// shared (permuted read: 32 scalars/block, negligible); 16 independent
// STG.128 streams per thread with __stcs (write-once output, 2x L2).
// ---------------------------------------------------------------------------
#define K3_ROWS   16
#define K3_CHUNKS (E_DIM / (256 * 4))   // 4 column chunks of 1024 floats

__global__ void __launch_bounds__(256) broadcast_kernel(
        const float* __restrict__ M_prev, float* __restrict__ out) {
    __shared__ float sA[K3_ROWS];
    __shared__ float sB[K3_ROWS];

    const int t0 = blockIdx.y * K3_ROWS;      // multiple of 16
    const int grp = t0 >> 4;                  // PERM(t0+r) = r*1024 + grp
    if (threadIdx.x < K3_ROWS) {
        sA[threadIdx.x] = g_A[threadIdx.x * 1024 + grp];
    } else if (threadIdx.x < 2 * K3_ROWS) {
        int r = threadIdx.x - K3_ROWS;
        sB[r] = g_B[r * 1024 + grp];
    }

    const int col = blockIdx.x * 256 + threadIdx.x;   // float4 column index
    float4 m = __ldg(&((const float4*)M_prev)[col]);
    __syncthreads();

    float4* o4 = (float4*)out;
    #pragma unroll
    for (int r = 0; r < K3_ROWS; r++) {
        float a = sA[r];
        float b = sB[r];
        float4 v;
        v.x = fmaf(a, m.x, b);
        v.y = fmaf(a, m.y, b);
        v.z = fmaf(a, m.z, b);
        v.w = fmaf(a, m.w, b);
        __stcs(&o4[(size_t)(t0 + r) * (E_DIM / 4) + col], v);
    }
}

// ---------------------------------------------------------------------------
extern "C" void kernel_launch(void* const* d_in, const int* in_sizes, int n_in,
                              void* d_out, int out_size) {
    const int*   indices = (const int*)d_in[0];   // (T, B) int32 (JAX downcast)
    const float* M_prev  = (const float*)d_in[1]; // (E,)   f32
    const float* params  = (const float*)d_in[2]; // (N, 2) f32
    float*       out     = (float*)d_out;         // (T, E) f32

    gather_reduce_kernel<<<(T_DIM / K1_ROWS * 32) / 256, 256>>>(indices, params);
    scan_kernel<<<1, 1024>>>();
    dim3 g3(K3_CHUNKS, T_DIM / K3_ROWS);
    broadcast_kernel<<<g3, 256>>>(M_prev, out);
}

// round 8
// speedup vs baseline: 1.4498x; 1.0314x over previous
#include <cuda_runtime.h>
#include <cstdint>

// Problem shape (fixed by reference)
#define T_DIM 16384
#define B_DIM 64
#define E_DIM 4096

// Permuted scratch layout so the single-block scan kernel is fully coalesced:
//   P(t) = (t & 15) * 1024 + (t >> 4)
// Scan thread `tid` owns t = 16*tid + i (i=0..15) -> permuted addr i*1024+tid
// -> every warp access is one coalesced transaction.
__device__ __forceinline__ int PERM(int t) { return ((t & 15) << 10) | (t >> 4); }

// Scratch (allocation-free, per harness rules). Packed float2: (.x=alpha/A, .y=beta/B)
__device__ float2 g_ab[T_DIM];
__device__ float2 g_AB[T_DIM];

// ---------------------------------------------------------------------------
// Kernel 1: per-t gather + reduce over B=64.
// One warp per 2 t-rows, 4 independent float2 gathers per lane.
// 512-thread blocks -> ~55 warps/SM to hide the L1tex gather replays
// (~2 cyc/wavefront, ~1M wavefronts total -> ~7us structural floor).
// ---------------------------------------------------------------------------
#define K1_ROWS 2
__global__ void __launch_bounds__(512) gather_reduce_kernel(
        const int* __restrict__ indices, const float* __restrict__ params) {
    int gwarp = (blockIdx.x * blockDim.x + threadIdx.x) >> 5;
    int lane  = threadIdx.x & 31;
    int t0 = gwarp * K1_ROWS;

    const float2* p2 = (const float2*)params;

    int2 idx[K1_ROWS];
    #pragma unroll
    for (int r = 0; r < K1_ROWS; r++) {
        idx[r] = ((const int2*)(indices + (size_t)(t0 + r) * B_DIM))[lane];
    }

    float2 v0[K1_ROWS], v1[K1_ROWS];
    #pragma unroll
    for (int r = 0; r < K1_ROWS; r++) v0[r] = __ldg(&p2[idx[r].x]);
    #pragma unroll
    for (int r = 0; r < K1_ROWS; r++) v1[r] = __ldg(&p2[idx[r].y]);

    #pragma unroll
    for (int r = 0; r < K1_ROWS; r++) {
        float sa = v0[r].x + v1[r].x;
        float sb = v0[r].y + v1[r].y;
        #pragma unroll
        for (int off = 16; off > 0; off >>= 1) {
            sa += __shfl_xor_sync(0xFFFFFFFFu, sa, off);
            sb += __shfl_xor_sync(0xFFFFFFFFu, sb, off);
        }
        if (lane == 0) {
            g_ab[PERM(t0 + r)] = make_float2(sa, sb);
        }
    }
}

// ---------------------------------------------------------------------------
// Kernel 2: linear-recurrence scan over T=16384.
// Single block, 1024 threads, 16 elements/thread, shuffle-based block scan
// (2 barriers instead of 20). Compose is ordered:
//   compose(earlier=(A,B), later=(a,b)) = (a*A, a*B + b)
// ---------------------------------------------------------------------------
__global__ void __launch_bounds__(1024) scan_kernel() {
    __shared__ float2 sW[32];   // per-warp inclusive totals

    const int tid  = threadIdx.x;
    const int lane = tid & 31;
    const int wid  = tid >> 5;

    float2 e[16];
    #pragma unroll
    for (int i = 0; i < 16; i++) e[i] = g_ab[i * 1024 + tid];

    // thread-local inclusive aggregate (in order)
    float ca = 1.0f, cb = 0.0f;
    #pragma unroll
    for (int i = 0; i < 16; i++) {
        cb = fmaf(e[i].x, cb, e[i].y);
        ca = e[i].x * ca;
    }

    // warp inclusive scan over thread aggregates (shfl_up, order-preserving)
    float wa = ca, wb = cb;
    #pragma unroll
    for (int off = 1; off < 32; off <<= 1) {
        float pa = __shfl_up_sync(0xFFFFFFFFu, wa, off);
        float pb = __shfl_up_sync(0xFFFFFFFFu, wb, off);
        if (lane >= off) {
            wb = fmaf(ca, pb, wb);   // later=(ca,cb-part already in wa/wb)
            wa = ca * pa;
            // NOTE: must use the ORIGINAL local aggregate? No — standard
            // scan: new = compose(prev_inclusive_from_lower, my_inclusive).
            // compose((pa,pb),(wa,wb)) = (wa*pa, wa*pb + wb). Fix below.
        }
        // recompute properly (avoid the aliasing above):
    }
    // The loop above risks mis-ordering; redo cleanly:
    wa = ca; wb = cb;
    #pragma unroll
    for (int off = 1; off < 32; off <<= 1) {
        float pa = __shfl_up_sync(0xFFFFFFFFu, wa, off);
        float pb = __shfl_up_sync(0xFFFFFFFFu, wb, off);
        float na = (lane >= off) ? wa * pa : wa;
        float nb = (lane >= off) ? fmaf(wa, pb, wb) : wb;
        wa = na; wb = nb;
    }

    if (lane == 31) sW[wid] = make_float2(wa, wb);
    __syncthreads();

    // warp 0 scans the 32 warp totals (inclusive)
    if (wid == 0) {
        float xa = sW[lane].x, xb = sW[lane].y;
        #pragma unroll
        for (int off = 1; off < 32; off <<= 1) {
            float pa = __shfl_up_sync(0xFFFFFFFFu, xa, off);
            float pb = __shfl_up_sync(0xFFFFFFFFu, xb, off);
            float na = (lane >= off) ? xa * pa : xa;
            float nb = (lane >= off) ? fmaf(xa, pb, xb) : xb;
            xa = na; xb = nb;
        }
        sW[lane] = make_float2(xa, xb);
    }
    __syncthreads();

    // block-exclusive prefix for this thread:
    //   warp_prefix (warps before wid) composed with lane-exclusive scan
    float wpa = (wid > 0) ? sW[wid - 1].x : 1.0f;
    float wpb = (wid > 0) ? sW[wid - 1].y : 0.0f;
    float lea = __shfl_up_sync(0xFFFFFFFFu, wa, 1);
    float leb = __shfl_up_sync(0xFFFFFFFFu, wb, 1);
    if (lane == 0) { lea = 1.0f; leb = 0.0f; }
    // compose(earlier=warp_prefix, later=lane_exclusive)
    float pa = lea * wpa;
    float pb = fmaf(lea, wpb, leb);

    // replay local elements applying prefix; coalesced permuted writes
    #pragma unroll
    for (int i = 0; i < 16; i++) {
        pb = fmaf(e[i].x, pb, e[i].y);
        pa = e[i].x * pa;
        g_AB[i * 1024 + tid] = make_float2(pa, pb);
    }
}

// ---------------------------------------------------------------------------
// Kernel 3: output broadcast.  out[t, e] = A[t] * M_prev[e] + B[t]
// Block = one E-chunk (1024 floats as float4) x 16 t-rows; A/B staged to
// shared; 16 independent STG.128 streams/thread with __stcs.
// This kernel IS the HBM-write roofline (~6.7 TB/s achieved).
// ---------------------------------------------------------------------------
#define K3_ROWS   16
#define K3_CHUNKS (E_DIM / (256 * 4))   // 4 column chunks of 1024 floats

__global__ void __launch_bounds__(256) broadcast_kernel(
        const float* __restrict__ M_prev, float* __restrict__ out) {
    __shared__ float2 sAB[K3_ROWS];

    const int t0  = blockIdx.y * K3_ROWS;   // multiple of 16
    const int grp = t0 >> 4;                // PERM(t0+r) = r*1024 + grp
    if (threadIdx.x < K3_ROWS) {
        sAB[threadIdx.x] = g_AB[threadIdx.x * 1024 + grp];
    }

    const int col = blockIdx.x * 256 + threadIdx.x;   // float4 column index
    float4 m = __ldg(&((const float4*)M_prev)[col]);
    __syncthreads();

    float4* o4 = (float4*)out;
    #pragma unroll
    for (int r = 0; r < K3_ROWS; r++) {
        float a = sAB[r].x;
        float b = sAB[r].y;
        float4 v;
        v.x = fmaf(a, m.x, b);
        v.y = fmaf(a, m.y, b);
        v.z = fmaf(a, m.z, b);
        v.w = fmaf(a, m.w, b);
        __stcs(&o4[(size_t)(t0 + r) * (E_DIM / 4) + col], v);
    }
}

// ---------------------------------------------------------------------------
extern "C" void kernel_launch(void* const* d_in, const int* in_sizes, int n_in,
                              void* d_out, int out_size) {
    const int*   indices = (const int*)d_in[0];   // (T, B) int32 (JAX downcast)
    const float* M_prev  = (const float*)d_in[1]; // (E,)   f32
    const float* params  = (const float*)d_in[2]; // (N, 2) f32
    float*       out     = (float*)d_out;         // (T, E) f32

    // K1: 8192 warps (2 rows each), 512-thread blocks -> 512 blocks, ~86% occ
    gather_reduce_kernel<<<T_DIM / K1_ROWS * 32 / 512, 512>>>(indices, params);

    // K2: single-block shuffle scan
    scan_kernel<<<1, 1024>>>();

    // K3: (4 column chunks) x (1024 row groups)
    dim3 g3(K3_CHUNKS, T_DIM / K3_ROWS);
    broadcast_kernel<<<g3, 256>>>(M_prev, out);
}